// round 2
// baseline (speedup 1.0000x reference)
#include <cuda_runtime.h>
#include <cstddef>

#define N_NODES 100000
#define N_EDGES 1600000
#define N_GRAPHS 256
#define HID 128
#define BN_EPS 1e-5f

// ---------------- scratch (device globals; no allocation allowed) ----------------
__device__ float g_agg[(size_t)N_NODES * HID];   // aggregation buffer; reused as z2 (GEMM2 out)
__device__ float g_z1 [(size_t)N_NODES * HID];   // GEMM1 out
__device__ float g_h  [(size_t)N_NODES * HID];   // layer output features
__device__ float g_stats[2 * HID];               // per-channel sum, sumsq
__device__ float g_sb[2 * HID];                  // per-channel scale, shift
__device__ float g_pool[N_GRAPHS * HID];
__device__ float g_cnt[N_GRAPHS];

// ---------------- small utility kernels ----------------
__global__ void zero_kernel(float* p, int n) {
    int i = blockIdx.x * blockDim.x + threadIdx.x;
    if (i < n) p[i] = 0.f;
}

__global__ void copy4_kernel(float4* __restrict__ dst, const float4* __restrict__ src, int n4) {
    int i = blockIdx.x * blockDim.x + threadIdx.x;
    if (i < n4) dst[i] = src[i];
}

// vectorized fp32 reduction (sm_90+): 1 instruction instead of 4 scalar RED
__device__ __forceinline__ void red_add_v4(float* p, float4 v) {
    asm volatile("red.global.add.v4.f32 [%0], {%1, %2, %3, %4};"
                 :: "l"(p), "f"(v.x), "f"(v.y), "f"(v.z), "f"(v.w)
                 : "memory");
}

// ---------------- edge aggregation: agg[dst] += h[src] ----------------
// one thread per (edge, 4-channel group); 2^LOG_C4 groups per edge
template<int LOG_C4>
__global__ void edge_agg_kernel(const float* __restrict__ h, const int* __restrict__ ei) {
    unsigned i = blockIdx.x * blockDim.x + threadIdx.x;
    const unsigned total = ((unsigned)N_EDGES) << LOG_C4;
    if (i >= total) return;
    unsigned e = i >> LOG_C4;
    unsigned q = i & ((1u << LOG_C4) - 1u);
    const int C = 4 << LOG_C4;
    int s = __ldg(&ei[e]);
    int d = __ldg(&ei[N_EDGES + e]);
    float4 v = *(const float4*)(h + (size_t)s * C + q * 4);
    red_add_v4(g_agg + (size_t)d * C + q * 4, v);
}

// ---------------- fp32 tiled GEMM: C[M,128] = act(A[M,K] @ W[K,128] + bias) ----------------
// BM=128, BN=128 (full width), BK=16; 256 threads, 8x8 per thread
template<bool RELU>
__global__ __launch_bounds__(256) void gemm_kernel(
    const float* __restrict__ A, const float* __restrict__ W,
    const float* __restrict__ bias, float* __restrict__ C,
    int M, int K)
{
    __shared__ __align__(16) float As[16][132];   // [k][row], padded to kill store conflicts
    __shared__ __align__(16) float Bs[16][132];   // [k][col]

    const int tid = threadIdx.x;
    const int tx = tid & 15;         // col group
    const int ty = tid >> 4;         // row group
    const int blockRow = blockIdx.x * 128;

    float acc[8][8];
#pragma unroll
    for (int i = 0; i < 8; i++)
#pragma unroll
        for (int j = 0; j < 8; j++) acc[i][j] = 0.f;

    for (int k0 = 0; k0 < K; k0 += 16) {
        // load A tile (128x16) -> As transposed
#pragma unroll
        for (int t = 0; t < 2; t++) {
            int f = tid + t * 256;               // float4 index 0..511
            int row = f >> 2;                    // 0..127
            int kc = (f & 3) * 4;
            float4 v = make_float4(0.f, 0.f, 0.f, 0.f);
            int grow = blockRow + row;
            if (grow < M) v = *(const float4*)(A + (size_t)grow * K + k0 + kc);
            As[kc + 0][row] = v.x;
            As[kc + 1][row] = v.y;
            As[kc + 2][row] = v.z;
            As[kc + 3][row] = v.w;
        }
        // load W tile (16x128)
#pragma unroll
        for (int t = 0; t < 2; t++) {
            int f = tid + t * 256;
            int r = f >> 5;                      // 0..15
            int c = (f & 31) * 4;
            float4 v = *(const float4*)(W + (size_t)(k0 + r) * 128 + c);
            *(float4*)&Bs[r][c] = v;
        }
        __syncthreads();
#pragma unroll
        for (int k = 0; k < 16; k++) {
            float a[8], b[8];
            *(float4*)&a[0] = *(const float4*)&As[k][ty * 8];
            *(float4*)&a[4] = *(const float4*)&As[k][ty * 8 + 4];
            *(float4*)&b[0] = *(const float4*)&Bs[k][tx * 8];
            *(float4*)&b[4] = *(const float4*)&Bs[k][tx * 8 + 4];
#pragma unroll
            for (int i = 0; i < 8; i++)
#pragma unroll
                for (int j = 0; j < 8; j++)
                    acc[i][j] = fmaf(a[i], b[j], acc[i][j]);
        }
        __syncthreads();
    }

    float bb[8];
    *(float4*)&bb[0] = __ldg((const float4*)(bias + tx * 8));
    *(float4*)&bb[4] = __ldg((const float4*)(bias + tx * 8 + 4));

#pragma unroll
    for (int i = 0; i < 8; i++) {
        int grow = blockRow + ty * 8 + i;
        if (grow < M) {
            float o[8];
#pragma unroll
            for (int j = 0; j < 8; j++) {
                float v = acc[i][j] + bb[j];
                o[j] = RELU ? fmaxf(v, 0.f) : v;
            }
            *(float4*)(C + (size_t)grow * 128 + tx * 8)     = *(float4*)&o[0];
            *(float4*)(C + (size_t)grow * 128 + tx * 8 + 4) = *(float4*)&o[4];
        }
    }
}

// ---------------- BatchNorm statistics: per-channel sum & sumsq ----------------
__global__ void bn_stats_kernel(const float* __restrict__ z, int M) {
    int c = threadIdx.x & 127;
    int half = threadIdx.x >> 7;
    float s = 0.f, ss = 0.f;
    for (int r = blockIdx.x * 2 + half; r < M; r += gridDim.x * 2) {
        float v = z[(size_t)r * 128 + c];
        s += v;
        ss += v * v;
    }
    __shared__ float shs[2][128];
    __shared__ float shq[2][128];
    shs[half][c] = s;
    shq[half][c] = ss;
    __syncthreads();
    if (threadIdx.x < 128) {
        atomicAdd(&g_stats[c], shs[0][c] + shs[1][c]);
        atomicAdd(&g_stats[128 + c], shq[0][c] + shq[1][c]);
    }
}

// per-channel scale/shift from stats (avoids per-element rsqrt)
__global__ void bn_finalize_kernel(const float* __restrict__ gamma,
                                   const float* __restrict__ beta, int M) {
    int c = threadIdx.x;   // 128 threads
    float invM = 1.f / (float)M;
    float mean = g_stats[c] * invM;
    float var = g_stats[128 + c] * invM - mean * mean;
    float scale = gamma[c] * rsqrtf(var + BN_EPS);
    g_sb[c] = scale;
    g_sb[128 + c] = beta[c] - mean * scale;
}

// h = relu(z*scale + shift); optionally also seed next layer's agg buffer
__global__ void bn_apply_kernel(const float4* __restrict__ z, float4* __restrict__ h,
                                float4* __restrict__ agg, int n4) {
    int i = blockIdx.x * blockDim.x + threadIdx.x;
    if (i >= n4) return;
    int c = (i << 2) & 127;
    float4 v = z[i];
    float4 o;
    o.x = fmaxf(fmaf(v.x, g_sb[c + 0], g_sb[128 + c + 0]), 0.f);
    o.y = fmaxf(fmaf(v.y, g_sb[c + 1], g_sb[128 + c + 1]), 0.f);
    o.z = fmaxf(fmaf(v.z, g_sb[c + 2], g_sb[128 + c + 2]), 0.f);
    o.w = fmaxf(fmaf(v.w, g_sb[c + 3], g_sb[128 + c + 3]), 0.f);
    h[i] = o;
    if (agg) agg[i] = o;
}

// ---------------- global mean pool (sum + count via atomics) ----------------
__global__ void pool_kernel(const float* __restrict__ h, const int* __restrict__ batch) {
    unsigned t = blockIdx.x * blockDim.x + threadIdx.x;
    unsigned row = t >> 5;
    if (row >= N_NODES) return;
    int lane = t & 31;
    int g = __ldg(&batch[row]);
    float4 v = *(const float4*)(h + (size_t)row * 128 + lane * 4);
    red_add_v4(g_pool + g * 128 + lane * 4, v);
    if (lane == 0) atomicAdd(&g_cnt[g], 1.0f);
}

// ---------------- final projection: out[g] = (pool[g]/cnt[g]) @ W + b ----------------
__global__ void proj_kernel(const float* __restrict__ W, const float* __restrict__ b,
                            float* __restrict__ out) {
    __shared__ float hg[128];
    int g = blockIdx.x, c = threadIdx.x;
    float cnt = fmaxf(g_cnt[g], 1.0f);
    hg[c] = g_pool[g * 128 + c] / cnt;
    __syncthreads();
    float acc = b[c];
#pragma unroll 16
    for (int k = 0; k < 128; k++) acc = fmaf(hg[k], W[k * 128 + c], acc);
    out[g * 128 + c] = acc;
}

// ---------------- host launcher ----------------
extern "C" void kernel_launch(void* const* d_in, const int* in_sizes, int n_in,
                              void* d_out, int out_size) {
    const float* x     = (const float*)d_in[0];
    const int*   ei    = (const int*)  d_in[1];
    const int*   batch = (const int*)  d_in[2];
    const float* projw = (const float*)d_in[21];
    const float* projb = (const float*)d_in[22];

    float *agg, *z1, *h, *stats, *pool, *cnt;
    cudaGetSymbolAddress((void**)&agg,   g_agg);
    cudaGetSymbolAddress((void**)&z1,    g_z1);
    cudaGetSymbolAddress((void**)&h,     g_h);
    cudaGetSymbolAddress((void**)&stats, g_stats);
    cudaGetSymbolAddress((void**)&pool,  g_pool);
    cudaGetSymbolAddress((void**)&cnt,   g_cnt);

    const int M = N_NODES;
    const int gemmGrid = (M + 127) / 128;   // 782

    // zero pooling accumulators
    zero_kernel<<<(N_GRAPHS * HID + 255) / 256, 256>>>(pool, N_GRAPHS * HID);
    zero_kernel<<<1, 256>>>(cnt, N_GRAPHS);

    for (int l = 0; l < 3; l++) {
        const float* w1 = (const float*)d_in[3 + 6 * l + 0];
        const float* b1 = (const float*)d_in[3 + 6 * l + 1];
        const float* w2 = (const float*)d_in[3 + 6 * l + 2];
        const float* b2 = (const float*)d_in[3 + 6 * l + 3];
        const float* ga = (const float*)d_in[3 + 6 * l + 4];
        const float* be = (const float*)d_in[3 + 6 * l + 5];

        zero_kernel<<<1, 256>>>(stats, 2 * HID);

        if (l == 0) {
            // agg = x (64 ch), then agg[dst] += x[src]
            int n4 = M * 64 / 4;
            copy4_kernel<<<(n4 + 255) / 256, 256>>>((float4*)agg, (const float4*)x, n4);
            int items = N_EDGES * 16;
            edge_agg_kernel<4><<<(items + 255) / 256, 256>>>(x, ei);
            gemm_kernel<true ><<<gemmGrid, 256>>>(agg, w1, b1, z1, M, 64);
        } else {
            // agg already seeded with h by previous bn_apply; add edges
            int items = N_EDGES * 32;
            edge_agg_kernel<5><<<(items + 255) / 256, 256>>>(h, ei);
            gemm_kernel<true ><<<gemmGrid, 256>>>(agg, w1, b1, z1, M, 128);
        }
        gemm_kernel<false><<<gemmGrid, 256>>>(z1, w2, b2, agg, M, 128);   // z2 -> agg buffer

        bn_stats_kernel<<<512, 256>>>(agg, M);
        bn_finalize_kernel<<<1, 128>>>(ga, be, M);

        int n4 = M * HID / 4;
        float4* aggSeed = (l < 2) ? (float4*)agg : nullptr;  // seed next layer's agg = h
        bn_apply_kernel<<<(n4 + 255) / 256, 256>>>((const float4*)agg, (float4*)h, aggSeed, n4);
    }

    pool_kernel<<<(N_NODES * 32 + 255) / 256, 256>>>(h, batch);
    proj_kernel<<<N_GRAPHS, 128>>>(projw, projb, (float*)d_out);
}

// round 3
// speedup vs baseline: 1.3438x; 1.3438x over previous
#include <cuda_runtime.h>
#include <cstddef>
#include <cstdint>

#define N_NODES 100000
#define N_EDGES 1600000
#define N_GRAPHS 256
#define HID 128
#define BN_EPS 1e-5f

// ---------------- scratch (device globals; no allocation allowed) ----------------
__device__ float g_agg[(size_t)N_NODES * HID];   // aggregation buffer; reused as z2 (GEMM2 out)
__device__ float g_z1 [(size_t)N_NODES * HID];   // GEMM1 out
__device__ float g_h  [(size_t)N_NODES * HID];   // layer output features
__device__ float g_stats[2 * HID];               // per-channel sum, sumsq
__device__ float g_sb[2 * HID];                  // per-channel scale, shift
__device__ float g_pool[N_GRAPHS * HID];
__device__ float g_cnt[N_GRAPHS];

// ---------------- small utility kernels ----------------
__global__ void zero_kernel(float* p, int n) {
    int i = blockIdx.x * blockDim.x + threadIdx.x;
    if (i < n) p[i] = 0.f;
}

__global__ void copy4_kernel(float4* __restrict__ dst, const float4* __restrict__ src, int n4) {
    int i = blockIdx.x * blockDim.x + threadIdx.x;
    if (i < n4) dst[i] = src[i];
}

// vectorized fp32 reduction (sm_90+): 1 instruction instead of 4 scalar RED
__device__ __forceinline__ void red_add_v4(float* p, float4 v) {
    asm volatile("red.global.add.v4.f32 [%0], {%1, %2, %3, %4};"
                 :: "l"(p), "f"(v.x), "f"(v.y), "f"(v.z), "f"(v.w)
                 : "memory");
}

// ---------------- edge aggregation: agg[dst] += h[src] ----------------
template<int LOG_C4>
__global__ void edge_agg_kernel(const float* __restrict__ h, const int* __restrict__ ei) {
    unsigned i = blockIdx.x * blockDim.x + threadIdx.x;
    const unsigned total = ((unsigned)N_EDGES) << LOG_C4;
    if (i >= total) return;
    unsigned e = i >> LOG_C4;
    unsigned q = i & ((1u << LOG_C4) - 1u);
    const int C = 4 << LOG_C4;
    int s = __ldg(&ei[e]);
    int d = __ldg(&ei[N_EDGES + e]);
    float4 v = *(const float4*)(h + (size_t)s * C + q * 4);
    red_add_v4(g_agg + (size_t)d * C + q * 4, v);
}

// ---------------- TF32 tensor-core GEMM ----------------
// C[M,128] = act(A[M,K] @ W[K,128] + bias), K in {64,128}
// BM=128, BN=128 (full width). Whole A-tile + whole W staged in smem once.
// 256 threads = 8 warps in 4(m) x 2(n); warp tile 32x64 = 2 x 8 m16n8k8 atoms.
__device__ __forceinline__ float to_tf32(float x) {
    float y;
    asm("cvt.rna.tf32.f32 %0, %1;" : "=f"(y) : "f"(x));
    return y;
}

__device__ __forceinline__ void mma_tf32(float& c0, float& c1, float& c2, float& c3,
                                         uint32_t a0, uint32_t a1, uint32_t a2, uint32_t a3,
                                         uint32_t b0, uint32_t b1) {
    asm volatile("mma.sync.aligned.m16n8k8.row.col.f32.tf32.tf32.f32 "
                 "{%0,%1,%2,%3}, {%4,%5,%6,%7}, {%8,%9}, {%0,%1,%2,%3};"
                 : "+f"(c0), "+f"(c1), "+f"(c2), "+f"(c3)
                 : "r"(a0), "r"(a1), "r"(a2), "r"(a3), "r"(b0), "r"(b1));
}

template<int K, bool RELU>
__global__ __launch_bounds__(256) void gemm_tc_kernel(
    const float* __restrict__ A, const float* __restrict__ W,
    const float* __restrict__ bias, float* __restrict__ C, int M)
{
    // smem strides chosen for conflict-free fragment loads:
    //   SA mod 32 == 4  -> a-fragment bank == lane (perm)
    //   SB mod 32 == 8  -> b-fragment bank == 8*tig+g (perm)
    constexpr int SA = K + 4;       // 132 or 68
    constexpr int SB = 136;
    extern __shared__ float smem[];
    float* As = smem;               // [128][SA]
    float* Ws = smem + 128 * SA;    // [K][SB]

    const int tid = threadIdx.x;
    const int wid = tid >> 5;
    const int lane = tid & 31;
    const int g = lane >> 2;        // group id (0..7)
    const int tig = lane & 3;       // thread in group
    const int warp_m = wid >> 1;    // 0..3  -> rows warp_m*32
    const int warp_n = wid & 1;     // 0..1  -> cols warp_n*64
    const int blockRow = blockIdx.x * 128;

    // ---- stage A tile (128 x K) ----
    constexpr int KV4 = K / 4;
#pragma unroll
    for (int it = 0; it < K / 8; it++) {
        int f = tid + it * 256;                 // float4 index
        int row = f / KV4;
        int kc = (f % KV4) * 4;
        float4 v = make_float4(0.f, 0.f, 0.f, 0.f);
        int grow = blockRow + row;
        if (grow < M) v = *(const float4*)(A + (size_t)grow * K + kc);
        v.x = to_tf32(v.x); v.y = to_tf32(v.y); v.z = to_tf32(v.z); v.w = to_tf32(v.w);
        *(float4*)&As[row * SA + kc] = v;
    }
    // ---- stage W (K x 128) ----
#pragma unroll
    for (int it = 0; it < K / 8; it++) {
        int f = tid + it * 256;
        int row = f >> 5;
        int c = (f & 31) * 4;
        float4 v = *(const float4*)(W + (size_t)row * 128 + c);
        v.x = to_tf32(v.x); v.y = to_tf32(v.y); v.z = to_tf32(v.z); v.w = to_tf32(v.w);
        *(float4*)&Ws[row * SB + c] = v;
    }
    __syncthreads();

    const uint32_t* Au = (const uint32_t*)As;
    const uint32_t* Bu = (const uint32_t*)Ws;

    float acc[2][8][4];
#pragma unroll
    for (int i = 0; i < 2; i++)
#pragma unroll
        for (int j = 0; j < 8; j++)
#pragma unroll
            for (int r = 0; r < 4; r++) acc[i][j][r] = 0.f;

#pragma unroll 4
    for (int k0 = 0; k0 < K; k0 += 8) {
        uint32_t af[2][4];
#pragma unroll
        for (int ma = 0; ma < 2; ma++) {
            int mb = warp_m * 32 + ma * 16;
            af[ma][0] = Au[(mb + g)     * SA + k0 + tig];
            af[ma][1] = Au[(mb + g + 8) * SA + k0 + tig];
            af[ma][2] = Au[(mb + g)     * SA + k0 + tig + 4];
            af[ma][3] = Au[(mb + g + 8) * SA + k0 + tig + 4];
        }
        uint32_t bf[8][2];
#pragma unroll
        for (int nb = 0; nb < 8; nb++) {
            int col = warp_n * 64 + nb * 8 + g;
            bf[nb][0] = Bu[(k0 + tig)     * SB + col];
            bf[nb][1] = Bu[(k0 + tig + 4) * SB + col];
        }
#pragma unroll
        for (int ma = 0; ma < 2; ma++)
#pragma unroll
            for (int nb = 0; nb < 8; nb++)
                mma_tf32(acc[ma][nb][0], acc[ma][nb][1], acc[ma][nb][2], acc[ma][nb][3],
                         af[ma][0], af[ma][1], af[ma][2], af[ma][3],
                         bf[nb][0], bf[nb][1]);
    }

    // ---- epilogue: bias (+relu), write C ----
#pragma unroll
    for (int nb = 0; nb < 8; nb++) {
        int col = warp_n * 64 + nb * 8 + tig * 2;
        float b0 = __ldg(&bias[col]);
        float b1 = __ldg(&bias[col + 1]);
#pragma unroll
        for (int ma = 0; ma < 2; ma++) {
            int row0 = blockRow + warp_m * 32 + ma * 16 + g;
            int row1 = row0 + 8;
            float2 v0, v1;
            v0.x = acc[ma][nb][0] + b0; v0.y = acc[ma][nb][1] + b1;
            v1.x = acc[ma][nb][2] + b0; v1.y = acc[ma][nb][3] + b1;
            if (RELU) {
                v0.x = fmaxf(v0.x, 0.f); v0.y = fmaxf(v0.y, 0.f);
                v1.x = fmaxf(v1.x, 0.f); v1.y = fmaxf(v1.y, 0.f);
            }
            if (row0 < M) *(float2*)(C + (size_t)row0 * 128 + col) = v0;
            if (row1 < M) *(float2*)(C + (size_t)row1 * 128 + col) = v1;
        }
    }
}

// ---------------- BatchNorm statistics: per-channel sum & sumsq ----------------
__global__ void bn_stats_kernel(const float* __restrict__ z, int M) {
    int c = threadIdx.x & 127;
    int half = threadIdx.x >> 7;
    float s = 0.f, ss = 0.f;
    for (int r = blockIdx.x * 2 + half; r < M; r += gridDim.x * 2) {
        float v = z[(size_t)r * 128 + c];
        s += v;
        ss += v * v;
    }
    __shared__ float shs[2][128];
    __shared__ float shq[2][128];
    shs[half][c] = s;
    shq[half][c] = ss;
    __syncthreads();
    if (threadIdx.x < 128) {
        atomicAdd(&g_stats[c], shs[0][c] + shs[1][c]);
        atomicAdd(&g_stats[128 + c], shq[0][c] + shq[1][c]);
    }
}

__global__ void bn_finalize_kernel(const float* __restrict__ gamma,
                                   const float* __restrict__ beta, int M) {
    int c = threadIdx.x;   // 128 threads
    float invM = 1.f / (float)M;
    float mean = g_stats[c] * invM;
    float var = g_stats[128 + c] * invM - mean * mean;
    float scale = gamma[c] * rsqrtf(var + BN_EPS);
    g_sb[c] = scale;
    g_sb[128 + c] = beta[c] - mean * scale;
}

// h = relu(z*scale + shift); optionally also seed next layer's agg buffer
__global__ void bn_apply_kernel(const float4* __restrict__ z, float4* __restrict__ h,
                                float4* __restrict__ agg, int n4) {
    int i = blockIdx.x * blockDim.x + threadIdx.x;
    if (i >= n4) return;
    int c = (i << 2) & 127;
    float4 v = z[i];
    float4 o;
    o.x = fmaxf(fmaf(v.x, g_sb[c + 0], g_sb[128 + c + 0]), 0.f);
    o.y = fmaxf(fmaf(v.y, g_sb[c + 1], g_sb[128 + c + 1]), 0.f);
    o.z = fmaxf(fmaf(v.z, g_sb[c + 2], g_sb[128 + c + 2]), 0.f);
    o.w = fmaxf(fmaf(v.w, g_sb[c + 3], g_sb[128 + c + 3]), 0.f);
    h[i] = o;
    if (agg) agg[i] = o;
}

// ---------------- global mean pool (sum + count via atomics) ----------------
__global__ void pool_kernel(const float* __restrict__ h, const int* __restrict__ batch) {
    unsigned t = blockIdx.x * blockDim.x + threadIdx.x;
    unsigned row = t >> 5;
    if (row >= N_NODES) return;
    int lane = t & 31;
    int g = __ldg(&batch[row]);
    float4 v = *(const float4*)(h + (size_t)row * 128 + lane * 4);
    red_add_v4(g_pool + g * 128 + lane * 4, v);
    if (lane == 0) atomicAdd(&g_cnt[g], 1.0f);
}

// ---------------- final projection: out[g] = (pool[g]/cnt[g]) @ W + b ----------------
__global__ void proj_kernel(const float* __restrict__ W, const float* __restrict__ b,
                            float* __restrict__ out) {
    __shared__ float hg[128];
    int g = blockIdx.x, c = threadIdx.x;
    float cnt = fmaxf(g_cnt[g], 1.0f);
    hg[c] = g_pool[g * 128 + c] / cnt;
    __syncthreads();
    float acc = b[c];
#pragma unroll 16
    for (int k = 0; k < 128; k++) acc = fmaf(hg[k], W[k * 128 + c], acc);
    out[g * 128 + c] = acc;
}

// ---------------- host launcher ----------------
extern "C" void kernel_launch(void* const* d_in, const int* in_sizes, int n_in,
                              void* d_out, int out_size) {
    const float* x     = (const float*)d_in[0];
    const int*   ei    = (const int*)  d_in[1];
    const int*   batch = (const int*)  d_in[2];
    const float* projw = (const float*)d_in[21];
    const float* projb = (const float*)d_in[22];

    float *agg, *z1, *h, *stats, *pool, *cnt;
    cudaGetSymbolAddress((void**)&agg,   g_agg);
    cudaGetSymbolAddress((void**)&z1,    g_z1);
    cudaGetSymbolAddress((void**)&h,     g_h);
    cudaGetSymbolAddress((void**)&stats, g_stats);
    cudaGetSymbolAddress((void**)&pool,  g_pool);
    cudaGetSymbolAddress((void**)&cnt,   g_cnt);

    const int M = N_NODES;
    const int gemmGrid = (M + 127) / 128;   // 782

    // dynamic smem sizes for the tensor GEMMs
    const int smem128 = (128 * 132 + 128 * 136) * 4;   // 137216 B
    const int smem64  = (128 * 68  + 64  * 136) * 4;   // 69632 B
    cudaFuncSetAttribute(gemm_tc_kernel<128, true >, cudaFuncAttributeMaxDynamicSharedMemorySize, smem128);
    cudaFuncSetAttribute(gemm_tc_kernel<128, false>, cudaFuncAttributeMaxDynamicSharedMemorySize, smem128);
    cudaFuncSetAttribute(gemm_tc_kernel<64,  true >, cudaFuncAttributeMaxDynamicSharedMemorySize, smem64);

    // zero pooling accumulators
    zero_kernel<<<(N_GRAPHS * HID + 255) / 256, 256>>>(pool, N_GRAPHS * HID);
    zero_kernel<<<1, 256>>>(cnt, N_GRAPHS);

    for (int l = 0; l < 3; l++) {
        const float* w1 = (const float*)d_in[3 + 6 * l + 0];
        const float* b1 = (const float*)d_in[3 + 6 * l + 1];
        const float* w2 = (const float*)d_in[3 + 6 * l + 2];
        const float* b2 = (const float*)d_in[3 + 6 * l + 3];
        const float* ga = (const float*)d_in[3 + 6 * l + 4];
        const float* be = (const float*)d_in[3 + 6 * l + 5];

        zero_kernel<<<1, 256>>>(stats, 2 * HID);

        if (l == 0) {
            int n4 = M * 64 / 4;
            copy4_kernel<<<(n4 + 255) / 256, 256>>>((float4*)agg, (const float4*)x, n4);
            int items = N_EDGES * 16;
            edge_agg_kernel<4><<<(items + 255) / 256, 256>>>(x, ei);
            gemm_tc_kernel<64, true ><<<gemmGrid, 256, smem64 >>>(agg, w1, b1, z1, M);
        } else {
            int items = N_EDGES * 32;
            edge_agg_kernel<5><<<(items + 255) / 256, 256>>>(h, ei);
            gemm_tc_kernel<128, true ><<<gemmGrid, 256, smem128>>>(agg, w1, b1, z1, M);
        }
        gemm_tc_kernel<128, false><<<gemmGrid, 256, smem128>>>(z1, w2, b2, agg, M);  // z2 -> agg

        bn_stats_kernel<<<512, 256>>>(agg, M);
        bn_finalize_kernel<<<1, 128>>>(ga, be, M);

        int n4 = M * HID / 4;
        float4* aggSeed = (l < 2) ? (float4*)agg : nullptr;  // seed next layer's agg = h
        bn_apply_kernel<<<(n4 + 255) / 256, 256>>>((const float4*)agg, (float4*)h, aggSeed, n4);
    }

    pool_kernel<<<(N_NODES * 32 + 255) / 256, 256>>>(h, batch);
    proj_kernel<<<N_GRAPHS, 128>>>(projw, projb, (float*)d_out);
}

// round 7
// speedup vs baseline: 1.5666x; 1.1658x over previous
#include <cuda_runtime.h>
#include <cstddef>
#include <cstdint>

#define N_NODES 100000
#define N_EDGES 1600000
#define N_GRAPHS 256
#define HID 128
#define BN_EPS 1e-5f

// ---------------- scratch (device globals; no allocation allowed) ----------------
__device__ float g_agg[(size_t)N_NODES * HID];   // aggregation buffer; reused as z2 (GEMM2 out)
__device__ float g_z1 [(size_t)N_NODES * HID];   // GEMM1 out
__device__ float g_h  [(size_t)N_NODES * HID];   // layer output features
__device__ float g_stats[2 * HID];               // per-channel sum, sumsq
__device__ float g_sb[2 * HID];                  // per-channel scale, shift
__device__ float g_pool[N_GRAPHS * HID];
__device__ float g_cnt[N_GRAPHS];
// CSR scratch
__device__ int g_deg[N_NODES];
__device__ int g_off[N_NODES + 1];
__device__ int g_cursor[N_NODES];
__device__ int g_csr[N_EDGES];

// ---------------- small utility kernels ----------------
__global__ void zero_kernel(float* p, int n) {
    int i = blockIdx.x * blockDim.x + threadIdx.x;
    if (i < n) p[i] = 0.f;
}
__global__ void zeroi_kernel(int* p, int n) {
    int i = blockIdx.x * blockDim.x + threadIdx.x;
    if (i < n) p[i] = 0;
}

__device__ __forceinline__ void red_add_v4(float* p, float4 v) {
    asm volatile("red.global.add.v4.f32 [%0], {%1, %2, %3, %4};"
                 :: "l"(p), "f"(v.x), "f"(v.y), "f"(v.z), "f"(v.w)
                 : "memory");
}

// ---------------- CSR build: histogram, scan, scatter ----------------
__global__ void hist_kernel(const int* __restrict__ ei) {
    int e = blockIdx.x * blockDim.x + threadIdx.x;
    if (e < N_EDGES) atomicAdd(&g_deg[__ldg(&ei[N_EDGES + e])], 1);
}

// single-block exclusive scan over g_deg -> g_off (and g_cursor copy)
__global__ __launch_bounds__(1024) void scan_kernel() {
    const int T = 1024;
    int tid = threadIdx.x;
    const int chunk = (N_NODES + T - 1) / T;   // 98
    int base = tid * chunk;
    int lim = min(base + chunk, N_NODES);
    int s = 0;
    for (int i = base; i < lim; i++) s += g_deg[i];

    __shared__ int wsum[32];
    int lane = tid & 31, wid = tid >> 5;
    int v = s;
#pragma unroll
    for (int d = 1; d < 32; d <<= 1) {
        int t = __shfl_up_sync(0xffffffffu, v, d);
        if (lane >= d) v += t;
    }
    if (lane == 31) wsum[wid] = v;
    __syncthreads();
    if (wid == 0) {
        int w = wsum[lane];
#pragma unroll
        for (int d = 1; d < 32; d <<= 1) {
            int t = __shfl_up_sync(0xffffffffu, w, d);
            if (lane >= d) w += t;
        }
        wsum[lane] = w;
    }
    __syncthreads();
    int excl = (v - s) + (wid > 0 ? wsum[wid - 1] : 0);
    int run = excl;
    for (int i = base; i < lim; i++) {
        g_off[i] = run;
        g_cursor[i] = run;
        run += g_deg[i];
    }
    if (tid == T - 1) g_off[N_NODES] = run;
}

__global__ void scatter_kernel(const int* __restrict__ ei) {
    int e = blockIdx.x * blockDim.x + threadIdx.x;
    if (e >= N_EDGES) return;
    int d = __ldg(&ei[N_EDGES + e]);
    int p = atomicAdd(&g_cursor[d], 1);
    g_csr[p] = __ldg(&ei[e]);
}

// ---------------- aggregation: agg[n] = h[n] + sum_{s in N(n)} h[s] ----------------
// one warp per node; coalesced row reads, register accumulate, no float atomics
template<int C>
__global__ __launch_bounds__(256) void agg_gather_kernel(
    const float* __restrict__ h, float* __restrict__ agg)
{
    int warp = (blockIdx.x * blockDim.x + threadIdx.x) >> 5;
    if (warp >= N_NODES) return;
    int lane = threadIdx.x & 31;
    constexpr int L = C / 4;                 // active lanes (16 or 32)
    const bool active = lane < L;

    int start = __ldg(&g_off[warp]);
    int end   = __ldg(&g_off[warp + 1]);

    float4 acc = make_float4(0.f, 0.f, 0.f, 0.f);
    if (active) acc = *(const float4*)(h + (size_t)warp * C + lane * 4);  // self term

    for (int j = start; j < end; j += 32) {
        int cnt = min(32, end - j);
        int myidx = (lane < cnt) ? __ldg(&g_csr[j + lane]) : 0;
#pragma unroll 4
        for (int k = 0; k < cnt; k++) {
            int s = __shfl_sync(0xffffffffu, myidx, k);
            if (active) {
                float4 v = *(const float4*)(h + (size_t)s * C + lane * 4);
                acc.x += v.x; acc.y += v.y; acc.z += v.z; acc.w += v.w;
            }
        }
    }
    if (active) *(float4*)(agg + (size_t)warp * C + lane * 4) = acc;
}

// ---------------- TF32 tensor-core GEMM ----------------
__device__ __forceinline__ float to_tf32(float x) {
    float y;
    asm("cvt.rna.tf32.f32 %0, %1;" : "=f"(y) : "f"(x));
    return y;
}

__device__ __forceinline__ void mma_tf32(float& c0, float& c1, float& c2, float& c3,
                                         uint32_t a0, uint32_t a1, uint32_t a2, uint32_t a3,
                                         uint32_t b0, uint32_t b1) {
    asm volatile("mma.sync.aligned.m16n8k8.row.col.f32.tf32.tf32.f32 "
                 "{%0,%1,%2,%3}, {%4,%5,%6,%7}, {%8,%9}, {%0,%1,%2,%3};"
                 : "+f"(c0), "+f"(c1), "+f"(c2), "+f"(c3)
                 : "r"(a0), "r"(a1), "r"(a2), "r"(a3), "r"(b0), "r"(b1));
}

template<int K, bool RELU>
__global__ __launch_bounds__(256) void gemm_tc_kernel(
    const float* __restrict__ A, const float* __restrict__ W,
    const float* __restrict__ bias, float* __restrict__ C, int M)
{
    constexpr int SA = K + 4;       // 132 or 68 (mod 32 == 4: conflict-free a-frag)
    constexpr int SB = 136;         // mod 32 == 8: conflict-free b-frag
    extern __shared__ float smem[];
    float* As = smem;               // [128][SA]
    float* Ws = smem + 128 * SA;    // [K][SB]

    const int tid = threadIdx.x;
    const int wid = tid >> 5;
    const int lane = tid & 31;
    const int g = lane >> 2;
    const int tig = lane & 3;
    const int warp_m = wid >> 1;
    const int warp_n = wid & 1;
    const int blockRow = blockIdx.x * 128;

    constexpr int KV4 = K / 4;
#pragma unroll
    for (int it = 0; it < K / 8; it++) {
        int f = tid + it * 256;
        int row = f / KV4;
        int kc = (f % KV4) * 4;
        float4 v = make_float4(0.f, 0.f, 0.f, 0.f);
        int grow = blockRow + row;
        if (grow < M) v = *(const float4*)(A + (size_t)grow * K + kc);
        v.x = to_tf32(v.x); v.y = to_tf32(v.y); v.z = to_tf32(v.z); v.w = to_tf32(v.w);
        *(float4*)&As[row * SA + kc] = v;
    }
#pragma unroll
    for (int it = 0; it < K / 8; it++) {
        int f = tid + it * 256;
        int row = f >> 5;
        int c = (f & 31) * 4;
        float4 v = *(const float4*)(W + (size_t)row * 128 + c);
        v.x = to_tf32(v.x); v.y = to_tf32(v.y); v.z = to_tf32(v.z); v.w = to_tf32(v.w);
        *(float4*)&Ws[row * SB + c] = v;
    }
    __syncthreads();

    const uint32_t* Au = (const uint32_t*)As;
    const uint32_t* Bu = (const uint32_t*)Ws;

    float acc[2][8][4];
#pragma unroll
    for (int i = 0; i < 2; i++)
#pragma unroll
        for (int j = 0; j < 8; j++)
#pragma unroll
            for (int r = 0; r < 4; r++) acc[i][j][r] = 0.f;

#pragma unroll 4
    for (int k0 = 0; k0 < K; k0 += 8) {
        uint32_t af[2][4];
#pragma unroll
        for (int ma = 0; ma < 2; ma++) {
            int mb = warp_m * 32 + ma * 16;
            af[ma][0] = Au[(mb + g)     * SA + k0 + tig];
            af[ma][1] = Au[(mb + g + 8) * SA + k0 + tig];
            af[ma][2] = Au[(mb + g)     * SA + k0 + tig + 4];
            af[ma][3] = Au[(mb + g + 8) * SA + k0 + tig + 4];
        }
        uint32_t bf[8][2];
#pragma unroll
        for (int nb = 0; nb < 8; nb++) {
            int col = warp_n * 64 + nb * 8 + g;
            bf[nb][0] = Bu[(k0 + tig)     * SB + col];
            bf[nb][1] = Bu[(k0 + tig + 4) * SB + col];
        }
#pragma unroll
        for (int ma = 0; ma < 2; ma++)
#pragma unroll
            for (int nb = 0; nb < 8; nb++)
                mma_tf32(acc[ma][nb][0], acc[ma][nb][1], acc[ma][nb][2], acc[ma][nb][3],
                         af[ma][0], af[ma][1], af[ma][2], af[ma][3],
                         bf[nb][0], bf[nb][1]);
    }

#pragma unroll
    for (int nb = 0; nb < 8; nb++) {
        int col = warp_n * 64 + nb * 8 + tig * 2;
        float b0 = __ldg(&bias[col]);
        float b1 = __ldg(&bias[col + 1]);
#pragma unroll
        for (int ma = 0; ma < 2; ma++) {
            int row0 = blockRow + warp_m * 32 + ma * 16 + g;
            int row1 = row0 + 8;
            float2 v0, v1;
            v0.x = acc[ma][nb][0] + b0; v0.y = acc[ma][nb][1] + b1;
            v1.x = acc[ma][nb][2] + b0; v1.y = acc[ma][nb][3] + b1;
            if (RELU) {
                v0.x = fmaxf(v0.x, 0.f); v0.y = fmaxf(v0.y, 0.f);
                v1.x = fmaxf(v1.x, 0.f); v1.y = fmaxf(v1.y, 0.f);
            }
            if (row0 < M) *(float2*)(C + (size_t)row0 * 128 + col) = v0;
            if (row1 < M) *(float2*)(C + (size_t)row1 * 128 + col) = v1;
        }
    }
}

// ---------------- BatchNorm ----------------
__global__ void bn_stats_kernel(const float* __restrict__ z, int M) {
    int c = threadIdx.x & 127;
    int half = threadIdx.x >> 7;
    float s = 0.f, ss = 0.f;
    for (int r = blockIdx.x * 2 + half; r < M; r += gridDim.x * 2) {
        float v = z[(size_t)r * 128 + c];
        s += v;
        ss += v * v;
    }
    __shared__ float shs[2][128];
    __shared__ float shq[2][128];
    shs[half][c] = s;
    shq[half][c] = ss;
    __syncthreads();
    if (threadIdx.x < 128) {
        atomicAdd(&g_stats[c], shs[0][c] + shs[1][c]);
        atomicAdd(&g_stats[128 + c], shq[0][c] + shq[1][c]);
    }
}

__global__ void bn_finalize_kernel(const float* __restrict__ gamma,
                                   const float* __restrict__ beta, int M) {
    int c = threadIdx.x;
    float invM = 1.f / (float)M;
    float mean = g_stats[c] * invM;
    float var = g_stats[128 + c] * invM - mean * mean;
    float scale = gamma[c] * rsqrtf(var + BN_EPS);
    g_sb[c] = scale;
    g_sb[128 + c] = beta[c] - mean * scale;
}

__global__ void bn_apply_kernel(const float4* __restrict__ z, float4* __restrict__ h, int n4) {
    int i = blockIdx.x * blockDim.x + threadIdx.x;
    if (i >= n4) return;
    int c = (i << 2) & 127;
    float4 v = z[i];
    float4 o;
    o.x = fmaxf(fmaf(v.x, g_sb[c + 0], g_sb[128 + c + 0]), 0.f);
    o.y = fmaxf(fmaf(v.y, g_sb[c + 1], g_sb[128 + c + 1]), 0.f);
    o.z = fmaxf(fmaf(v.z, g_sb[c + 2], g_sb[128 + c + 2]), 0.f);
    o.w = fmaxf(fmaf(v.w, g_sb[c + 3], g_sb[128 + c + 3]), 0.f);
    h[i] = o;
}

// ---------------- global mean pool ----------------
__global__ void pool_kernel(const float* __restrict__ h, const int* __restrict__ batch) {
    unsigned t = blockIdx.x * blockDim.x + threadIdx.x;
    unsigned row = t >> 5;
    if (row >= N_NODES) return;
    int lane = t & 31;
    int g = __ldg(&batch[row]);
    float4 v = *(const float4*)(h + (size_t)row * 128 + lane * 4);
    red_add_v4(g_pool + g * 128 + lane * 4, v);
    if (lane == 0) atomicAdd(&g_cnt[g], 1.0f);
}

// ---------------- final projection ----------------
__global__ void proj_kernel(const float* __restrict__ W, const float* __restrict__ b,
                            float* __restrict__ out) {
    __shared__ float hg[128];
    int g = blockIdx.x, c = threadIdx.x;
    float cnt = fmaxf(g_cnt[g], 1.0f);
    hg[c] = g_pool[g * 128 + c] / cnt;
    __syncthreads();
    float acc = b[c];
#pragma unroll 16
    for (int k = 0; k < 128; k++) acc = fmaf(hg[k], W[k * 128 + c], acc);
    out[g * 128 + c] = acc;
}

// ---------------- host launcher ----------------
extern "C" void kernel_launch(void* const* d_in, const int* in_sizes, int n_in,
                              void* d_out, int out_size) {
    const float* x     = (const float*)d_in[0];
    const int*   ei    = (const int*)  d_in[1];
    const int*   batch = (const int*)  d_in[2];
    const float* projw = (const float*)d_in[21];
    const float* projb = (const float*)d_in[22];

    float *agg, *z1, *h, *stats, *pool, *cnt;
    int *deg;
    cudaGetSymbolAddress((void**)&agg,   g_agg);
    cudaGetSymbolAddress((void**)&z1,    g_z1);
    cudaGetSymbolAddress((void**)&h,     g_h);
    cudaGetSymbolAddress((void**)&stats, g_stats);
    cudaGetSymbolAddress((void**)&pool,  g_pool);
    cudaGetSymbolAddress((void**)&cnt,   g_cnt);
    cudaGetSymbolAddress((void**)&deg,   g_deg);

    const int M = N_NODES;
    const int gemmGrid = (M + 127) / 128;

    const int smem128 = (128 * 132 + 128 * 136) * 4;
    const int smem64  = (128 * 68  + 64  * 136) * 4;
    cudaFuncSetAttribute(gemm_tc_kernel<128, true >, cudaFuncAttributeMaxDynamicSharedMemorySize, smem128);
    cudaFuncSetAttribute(gemm_tc_kernel<128, false>, cudaFuncAttributeMaxDynamicSharedMemorySize, smem128);
    cudaFuncSetAttribute(gemm_tc_kernel<64,  true >, cudaFuncAttributeMaxDynamicSharedMemorySize, smem64);

    // ---- CSR build (per launch; deterministic up to fp-add order) ----
    zeroi_kernel<<<(N_NODES + 255) / 256, 256>>>(deg, N_NODES);
    hist_kernel<<<(N_EDGES + 255) / 256, 256>>>(ei);
    scan_kernel<<<1, 1024>>>();
    scatter_kernel<<<(N_EDGES + 255) / 256, 256>>>(ei);

    // zero pooling accumulators
    zero_kernel<<<(N_GRAPHS * HID + 255) / 256, 256>>>(pool, N_GRAPHS * HID);
    zero_kernel<<<1, 256>>>(cnt, N_GRAPHS);

    const int aggGrid = (N_NODES * 32 + 255) / 256;   // one warp per node

    for (int l = 0; l < 3; l++) {
        const float* w1 = (const float*)d_in[3 + 6 * l + 0];
        const float* b1 = (const float*)d_in[3 + 6 * l + 1];
        const float* w2 = (const float*)d_in[3 + 6 * l + 2];
        const float* b2 = (const float*)d_in[3 + 6 * l + 3];
        const float* ga = (const float*)d_in[3 + 6 * l + 4];
        const float* be = (const float*)d_in[3 + 6 * l + 5];

        zero_kernel<<<1, 256>>>(stats, 2 * HID);

        if (l == 0) {
            agg_gather_kernel<64><<<aggGrid, 256>>>(x, agg);
            gemm_tc_kernel<64, true ><<<gemmGrid, 256, smem64 >>>(agg, w1, b1, z1, M);
        } else {
            agg_gather_kernel<128><<<aggGrid, 256>>>(h, agg);
            gemm_tc_kernel<128, true ><<<gemmGrid, 256, smem128>>>(agg, w1, b1, z1, M);
        }
        gemm_tc_kernel<128, false><<<gemmGrid, 256, smem128>>>(z1, w2, b2, agg, M);

        bn_stats_kernel<<<512, 256>>>(agg, M);
        bn_finalize_kernel<<<1, 128>>>(ga, be, M);

        int n4 = M * HID / 4;
        bn_apply_kernel<<<(n4 + 255) / 256, 256>>>((const float4*)agg, (float4*)h, n4);
    }

    pool_kernel<<<(N_NODES * 32 + 255) / 256, 256>>>(h, batch);
    proj_kernel<<<N_GRAPHS, 128>>>(projw, projb, (float*)d_out);
}